// round 11
// baseline (speedup 1.0000x reference)
#include <cuda_runtime.h>
#include <cuda_bf16.h>
#include <cstdint>

#define NLEV 4
#define MAXS 792
#define TILE 256
#define NST  2
#define NBLOCKS 444   // 148 SMs x 3 blocks/SM (64.3 KB smem each)

// Packed table: level sizes 36/72/216/792 -> offsets 0/36/108/324, 1116 float2 (8.9KB)
#define T_OFF0 0
#define T_OFF1 36
#define T_OFF2 108
#define T_OFF3 324
#define T_TOT  1116

#define STAGE_BYTES 27648u

struct alignas(16) Stage {
    float2 nll[8][TILE];   // 16 KB (rows contiguous in gmem)
    int    nidx[8][TILE];  //  8 KB
    float2 pll[TILE];      //  2 KB
    int    pidx[TILE];     //  1 KB
};                          // 27648 B

struct alignas(16) Smem {
    Stage    stage[NST];    // 55296 B
    float2   tab[T_TOT];    //  8928 B
    uint64_t bar[NST];
    int      tiles[4];      // stolen tile id per local-tile-index & 3 (-1 = done)
};

__device__ unsigned int g_tile_ctr;

__global__ void heal_ctr_init() { g_tile_ctr = 0u; }

__device__ __forceinline__ uint32_t smem_u32(const void* p) {
    return (uint32_t)__cvta_generic_to_shared(p);
}
__device__ __forceinline__ void bulk_cp(void* dst, const void* src, uint32_t bytes, uint32_t mbar) {
    asm volatile(
        "cp.async.bulk.shared::cluster.global.mbarrier::complete_tx::bytes [%0], [%1], %2, [%3];"
        :: "r"(smem_u32(dst)), "l"(src), "r"(bytes), "r"(mbar) : "memory");
}
__device__ __forceinline__ void mbar_init(uint32_t mbar, uint32_t count) {
    asm volatile("mbarrier.init.shared.b64 [%0], %1;" :: "r"(mbar), "r"(count) : "memory");
}
__device__ __forceinline__ void mbar_expect_tx(uint32_t mbar, uint32_t bytes) {
    asm volatile("mbarrier.arrive.expect_tx.shared.b64 _, [%0], %1;" :: "r"(mbar), "r"(bytes) : "memory");
}
__device__ __forceinline__ void mbar_wait(uint32_t mbar, uint32_t parity) {
    asm volatile(
        "{\n\t"
        ".reg .pred P;\n\t"
        "WAIT_%=:\n\t"
        "mbarrier.try_wait.parity.acquire.cta.shared::cta.b64 P, [%0], %1, 0x989680;\n\t"
        "@P bra.uni DONE_%=;\n\t"
        "bra.uni WAIT_%=;\n\t"
        "DONE_%=:\n\t"
        "}"
        :: "r"(mbar), "r"(parity) : "memory");
}

// Issue the 18 bulk copies for (tile, level) into a stage (single thread).
__device__ __forceinline__ void issue_item(
    Stage* st, int l, int b0, uint32_t mbar,
    const float2* __restrict__ neigh_ll, const int* __restrict__ neigh_idx,
    const float2* __restrict__ pixel_ll, const int* __restrict__ pixel_idx, int B)
{
    mbar_expect_tx(mbar, STAGE_BYTES);
#pragma unroll
    for (int row = 0; row < 8; row++)
        bulk_cp(&st->nll[row][0],  neigh_ll  + (size_t)(l * 8 + row) * B + b0, TILE * 8u, mbar);
#pragma unroll
    for (int row = 0; row < 8; row++)
        bulk_cp(&st->nidx[row][0], neigh_idx + (size_t)(l * 8 + row) * B + b0, TILE * 4u, mbar);
    bulk_cp(&st->pll[0],  pixel_ll  + (size_t)l * B + b0, TILE * 8u, mbar);
    bulk_cp(&st->pidx[0], pixel_idx + (size_t)l * B + b0, TILE * 4u, mbar);
}

__global__ __launch_bounds__(TILE) void heal_encoding_steal(
    const float2* __restrict__ params2,      // [NLEV, MAXS] float2
    const float2* __restrict__ pixel_ll,     // [NLEV, B]
    const float2* __restrict__ neigh_ll,     // [NLEV, 8, B]
    const int*    __restrict__ pixel_idx,    // [NLEV, B]
    const int*    __restrict__ neigh_idx,    // [NLEV, 8, B]
    float*        __restrict__ out,          // [B, 8]  out[b, 4f+l]
    int B)
{
    extern __shared__ char smem_raw[];
    Smem& s = *reinterpret_cast<Smem*>(smem_raw);
    const int tid = threadIdx.x;
    const int toff[NLEV] = {T_OFF0, T_OFF1, T_OFF2, T_OFF3};

    const bool aligned = (B & 3) == 0;        // bulk-cp 16B gmem alignment
    const int  ntiles  = aligned ? (B / TILE) : 0;

    if (tid == 0) {
#pragma unroll
        for (int k = 0; k < NST; k++) mbar_init(smem_u32(&s.bar[k]), 1);
    }
    __syncthreads();   // init visible before any complete_tx

    if (tid == 0) {
        // prologue: steal first tile, issue its items 0 and 1
        const int t0 = (int)atomicAdd(&g_tile_ctr, 1u);
        const int v  = (t0 < ntiles) ? t0 : -1;
        s.tiles[0] = v;
        if (v >= 0) {
            issue_item(&s.stage[0], 0, v * TILE, smem_u32(&s.bar[0]),
                       neigh_ll, neigh_idx, pixel_ll, pixel_idx, B);
            issue_item(&s.stage[1], 1, v * TILE, smem_u32(&s.bar[1]),
                       neigh_ll, neigh_idx, pixel_ll, pixel_idx, B);
        }
    }

    // packed param table (level sizes 36/72/216/792), once per block
    {
        const int tsz[NLEV] = {36, 72, 216, 792};
#pragma unroll
        for (int l = 0; l < NLEV; l++)
            for (int i = tid; i < tsz[l]; i += TILE)
                s.tab[toff[l] + i] = params2[l * MAXS + i];
    }
    __syncthreads();   // table ready + s.tiles[0] visible

    float acc0[NLEV], acc1[NLEV];
    for (int i = 0; ; i++) {
        const int k    = i >> 2;
        const int tile = s.tiles[k & 3];
        if (tile < 0) break;                     // pipeline drained

        const int st_i = i & 1;
        mbar_wait(smem_u32(&s.bar[st_i]), (i >> 1) & 1);

        const int lvl = i & 3;
        Stage* st = &s.stage[st_i];
        const float2 pl = st->pll[tid];
        const int    p  = st->pidx[tid];
        const float2 r  = s.tab[toff[lvl] + p];
        float s0 = r.x, s1 = r.y;
#pragma unroll
        for (int j = 0; j < 8; j++) {
            const int    n  = st->nidx[j][tid];
            const float2 ll = st->nll[j][tid];
            const float dphi = ll.y - pl.y;
            const float dth  = ll.x - pl.x;
            float w = rsqrtf(fmaf(dphi, dphi, dth * dth));
            w = (n >= 0) ? w : 0.0f;
            const float2 v = s.tab[toff[lvl] + (n >= 0 ? n : 0)];
            s0 = fmaf(w, v.x, s0);
            s1 = fmaf(w, v.y, s1);
        }
        acc0[lvl] = s0; acc1[lvl] = s1;

        if (lvl == 3) {
            const int b = tile * TILE + tid;
            float4* op = reinterpret_cast<float4*>(out + (size_t)b * 8);
            op[0] = make_float4(acc0[0], acc0[1], acc0[2], acc0[3]);
            op[1] = make_float4(acc1[0], acc1[1], acc1[2], acc1[3]);
        }

        __syncthreads();   // all readers done with stage st_i; orders s.tiles STS
        if (tid == 0) {
            const int ni = i + 2;
            const int kn = ni >> 2;
            int ntile;
            if ((ni & 3) == 0) {                 // first item of local tile kn: steal
                const int t = (int)atomicAdd(&g_tile_ctr, 1u);
                ntile = (t < ntiles) ? t : -1;
                s.tiles[kn & 3] = ntile;
            } else {
                ntile = s.tiles[kn & 3];
            }
            if (ntile >= 0)
                issue_item(&s.stage[ni & 1], ni & 3, ntile * TILE,
                           smem_u32(&s.bar[ni & 1]),
                           neigh_ll, neigh_idx, pixel_ll, pixel_idx, B);
        }
    }

    // tail (B % TILE samples; whole range if unaligned), grid-strided
    const int tail_start = aligned ? ntiles * TILE : 0;
    for (int b = tail_start + blockIdx.x * TILE + tid; b < B; b += gridDim.x * TILE) {
        float t0[NLEV], t1[NLEV];
#pragma unroll
        for (int l = 0; l < NLEV; l++) {
            int    nidx[8];
            float2 nll[8];
#pragma unroll
            for (int j = 0; j < 8; j++)
                nidx[j] = __ldcs(neigh_idx + (size_t)(l * 8 + j) * B + b);
#pragma unroll
            for (int j = 0; j < 8; j++)
                nll[j] = __ldcs(neigh_ll + (size_t)(l * 8 + j) * B + b);
            const int    p  = __ldcs(pixel_idx + (size_t)l * B + b);
            const float2 pl = __ldcs(pixel_ll + (size_t)l * B + b);
            const float2 r  = s.tab[toff[l] + p];
            float s0 = r.x, s1 = r.y;
#pragma unroll
            for (int j = 0; j < 8; j++) {
                const float dphi = nll[j].y - pl.y;
                const float dth  = nll[j].x - pl.x;
                float w = rsqrtf(fmaf(dphi, dphi, dth * dth));
                w = (nidx[j] >= 0) ? w : 0.0f;
                const float2 v = s.tab[toff[l] + (nidx[j] >= 0 ? nidx[j] : 0)];
                s0 = fmaf(w, v.x, s0);
                s1 = fmaf(w, v.y, s1);
            }
            t0[l] = s0; t1[l] = s1;
        }
        float4* op = reinterpret_cast<float4*>(out + (size_t)b * 8);
        op[0] = make_float4(t0[0], t0[1], t0[2], t0[3]);
        op[1] = make_float4(t1[0], t1[1], t1[2], t1[3]);
    }
}

extern "C" void kernel_launch(void* const* d_in, const int* in_sizes, int n_in,
                              void* d_out, int out_size)
{
    // metadata order: params, pixel_latlon, neigh_latlon, pixel_index, neigh_index
    const float2* params2   = (const float2*)d_in[0];
    const float2* pixel_ll  = (const float2*)d_in[1];
    const float2* neigh_ll  = (const float2*)d_in[2];
    const int*    pixel_idx = (const int*)d_in[3];
    const int*    neigh_idx = (const int*)d_in[4];
    float*        out       = (float*)d_out;

    const int B = in_sizes[3] / NLEV;   // pixel_index has NLEV*B elements

    cudaFuncSetAttribute(heal_encoding_steal,
                         cudaFuncAttributeMaxDynamicSharedMemorySize, sizeof(Smem));

    heal_ctr_init<<<1, 1>>>();
    heal_encoding_steal<<<NBLOCKS, TILE, sizeof(Smem)>>>(
        params2, pixel_ll, neigh_ll, pixel_idx, neigh_idx, out, B);
}

// round 12
// speedup vs baseline: 1.1698x; 1.1698x over previous
#include <cuda_runtime.h>
#include <cuda_bf16.h>
#include <cstdint>

#define NLEV 4
#define MAXS 792
#define NTHREADS 256

// Packed table: level sizes 36/72/216/792 -> offsets 0/36/108/324, 1116 float2 (8.9KB)
#define T_TOT 1116

// R11: no smem staging for streamed data. Register software pipeline:
// while computing level l, level l+1's 18 loads are in flight.
// Only the packed param table lives in smem.
__global__ __launch_bounds__(NTHREADS, 3) void heal_encoding_regpipe(
    const float2* __restrict__ params2,      // [NLEV, MAXS] float2
    const float2* __restrict__ pixel_ll,     // [NLEV, B]
    const float2* __restrict__ neigh_ll,     // [NLEV, 8, B]
    const int*    __restrict__ pixel_idx,    // [NLEV, B]
    const int*    __restrict__ neigh_idx,    // [NLEV, 8, B]
    float*        __restrict__ out,          // [B, 8]  out[b, 4f+l]
    int B)
{
    __shared__ float2 tab[T_TOT];
    __shared__ int    toff_s[NLEV];          // keep toff out of the reg budget
    {
        const int tsz[NLEV]  = {36, 72, 216, 792};
        const int toff[NLEV] = {0, 36, 108, 324};
        if (threadIdx.x < NLEV) toff_s[threadIdx.x] = toff[threadIdx.x];
#pragma unroll
        for (int l = 0; l < NLEV; l++)
            for (int i = threadIdx.x; i < tsz[l]; i += NTHREADS)
                tab[toff[l] + i] = params2[l * MAXS + i];
    }
    __syncthreads();

    const int b = blockIdx.x * NTHREADS + threadIdx.x;
    if (b >= B) return;

    // double-buffered per-level inputs (registers)
    int    nidx[2][8];
    float2 nll [2][8];
    int    p   [2];
    float2 pl  [2];

    // prologue: load level 0 into buffer 0
#pragma unroll
    for (int j = 0; j < 8; j++)
        nidx[0][j] = __ldcs(neigh_idx + (size_t)(0 * 8 + j) * B + b);
#pragma unroll
    for (int j = 0; j < 8; j++)
        nll[0][j]  = __ldcs(neigh_ll  + (size_t)(0 * 8 + j) * B + b);
    p[0]  = __ldcs(pixel_idx + (size_t)0 * B + b);
    pl[0] = __ldcs(pixel_ll  + (size_t)0 * B + b);

    float acc0[NLEV], acc1[NLEV];

#pragma unroll
    for (int l = 0; l < NLEV; l++) {
        const int cur = l & 1;
        const int nxt = cur ^ 1;

        // issue next level's loads first (consumed next iteration)
        if (l + 1 < NLEV) {
#pragma unroll
            for (int j = 0; j < 8; j++)
                nidx[nxt][j] = __ldcs(neigh_idx + (size_t)((l + 1) * 8 + j) * B + b);
#pragma unroll
            for (int j = 0; j < 8; j++)
                nll[nxt][j]  = __ldcs(neigh_ll  + (size_t)((l + 1) * 8 + j) * B + b);
            p[nxt]  = __ldcs(pixel_idx + (size_t)(l + 1) * B + b);
            pl[nxt] = __ldcs(pixel_ll  + (size_t)(l + 1) * B + b);
        }

        // compute level l from buffer cur (its loads completed during level l-1)
        const int    to = toff_s[l];
        const float2 P  = pl[cur];
        const float2 r  = tab[to + p[cur]];
        float s0 = r.x, s1 = r.y;
#pragma unroll
        for (int j = 0; j < 8; j++) {
            const int    n  = nidx[cur][j];
            const float2 ll = nll[cur][j];
            const float dphi = ll.y - P.y;
            const float dth  = ll.x - P.x;
            float w = rsqrtf(fmaf(dphi, dphi, dth * dth));
            w = (n >= 0) ? w : 0.0f;
            const float2 v = tab[to + (n >= 0 ? n : 0)];
            s0 = fmaf(w, v.x, s0);
            s1 = fmaf(w, v.y, s1);
        }
        acc0[l] = s0;
        acc1[l] = s1;
    }

    // out[b, 4f + l]: 8 contiguous floats -> two float4 stores
    float4* op = reinterpret_cast<float4*>(out + (size_t)b * 8);
    op[0] = make_float4(acc0[0], acc0[1], acc0[2], acc0[3]);
    op[1] = make_float4(acc1[0], acc1[1], acc1[2], acc1[3]);
}

extern "C" void kernel_launch(void* const* d_in, const int* in_sizes, int n_in,
                              void* d_out, int out_size)
{
    // metadata order: params, pixel_latlon, neigh_latlon, pixel_index, neigh_index
    const float2* params2   = (const float2*)d_in[0];
    const float2* pixel_ll  = (const float2*)d_in[1];
    const float2* neigh_ll  = (const float2*)d_in[2];
    const int*    pixel_idx = (const int*)d_in[3];
    const int*    neigh_idx = (const int*)d_in[4];
    float*        out       = (float*)d_out;

    const int B = in_sizes[3] / NLEV;   // pixel_index has NLEV*B elements

    const int grid = (B + NTHREADS - 1) / NTHREADS;
    heal_encoding_regpipe<<<grid, NTHREADS>>>(
        params2, pixel_ll, neigh_ll, pixel_idx, neigh_idx, out, B);
}